// round 7
// baseline (speedup 1.0000x reference)
#include <cuda_runtime.h>
#include <math.h>
#include <stdint.h>

#define B     32
#define TENC  256
#define TOUT  400
#define EMB   512
#define NMEL  80
#define PN    256
#define ARNN  1024
#define DRNN  1024
#define AD    128
#define NF    32
#define KSZ   31

#define NBLK  148
#define NTHR  512
#define NWRP  (NBLK * 16)

#define ATT_TASKS  (ARNN * B)          // 32768
#define CONV_TASKS (B * TENC)          // 8192
#define DEC_TASKS  (DRNN * B)          // 32768
#define PA_ALL     (ATT_TASKS + CONV_TASKS + DEC_TASKS)
#define PROJ_TASKS ((NMEL + 1) * B)    // 2592

#define GATE_OFF  ((size_t)B * NMEL * TOUT)
#define ALIGN_OFF (GATE_OFF + (size_t)B * TOUT)

// ---------------- device scratch ----------------
__device__ __align__(16) float g_xs[(size_t)TOUT * B * PN];
__device__ __align__(16) float g_keys[(size_t)B * TENC * AD];
__device__ __align__(16) float g_loc[(size_t)B * TENC * AD];
__device__ __align__(16) float g_ah[2][B * ARNN];
__device__ __align__(16) float g_ac[B * ARNN];
__device__ __align__(16) float g_dh[2][B * DRNN];
__device__ __align__(16) float g_dc[B * DRNN];
__device__ __align__(16) float g_ctx[2][B * EMB];
__device__ __align__(16) float g_aw[B * TENC];
__device__ __align__(16) float g_awc[B * TENC];
__device__ __align__(16) float g_w1T[NMEL * PN];   // [k<80][m<256]
__device__ __align__(16) float g_w2T[PN * PN];     // [k][m]
__device__ __align__(16) float g_wkT[EMB * AD];    // [k<512][d<128]

__device__ unsigned g_cnt = 0;
__device__ volatile unsigned g_gen = 0;

// ---------------- helpers ----------------
__device__ __forceinline__ void grid_sync() {
    __syncthreads();
    if (threadIdx.x == 0) {
        __threadfence();
        unsigned gen = g_gen;
        if (atomicAdd(&g_cnt, 1u) == gridDim.x - 1u) {
            g_cnt = 0;
            __threadfence();
            g_gen = gen + 1u;
        } else {
            while (g_gen == gen) { __nanosleep(32); }
            __threadfence();
        }
    }
    __syncthreads();
}

__device__ __forceinline__ float wredsum(float v) {
#pragma unroll
    for (int o = 16; o > 0; o >>= 1) v += __shfl_xor_sync(0xffffffffu, v, o);
    return v;
}

__device__ __forceinline__ float sig_(float x) { return 1.0f / (1.0f + expf(-x)); }

// warp-cooperative dot: lanes stride float4s; w row warp-uniform, x broadcast
__device__ __forceinline__ float dot4(const float* __restrict__ w,
                                      const float* __restrict__ x,
                                      int n4, float acc, int lane) {
    const float4* w4 = (const float4*)w;
    const float4* x4 = (const float4*)x;
#pragma unroll 4
    for (int i = lane; i < n4; i += 32) {
        float4 a = w4[i];
        float4 b = x4[i];
        acc = fmaf(a.x, b.x, acc);
        acc = fmaf(a.y, b.y, acc);
        acc = fmaf(a.z, b.z, acc);
        acc = fmaf(a.w, b.w, acc);
    }
    return acc;
}

// ---------------- params ----------------
struct Params {
    const float* memory;       // (B,TENC,EMB)
    const float* dec_inputs;   // (B,TOUT,NMEL)
    const int*   mlen;         // (B,)
    const float* att_wih;      // (4096,768)
    const float* att_whh;      // (4096,1024)
    const float* att_bih;
    const float* att_bhh;
    const float* wq;           // (128,1024)
    const float* conv_w;       // (32,2,31)
    const float* conv_b;       // (32,)
    const float* wloc;         // (128,32)
    const float* wv;           // (1,128)
    const float* dec_wih;      // (4096,1536)
    const float* dec_whh;      // (4096,1024)
    const float* dec_bih;
    const float* dec_bhh;
    const float* wproj;        // (80,1536)
    const float* bproj;        // (80,)
    const float* wgate;        // (1,1536)
    const float* bgate;        // (1,)
    float*       out;
};

// ---------------- pre-kernels ----------------
__global__ void k_trans_w1(const float* __restrict__ w) {   // (256,80) -> [k][m]
    int i = blockIdx.x * blockDim.x + threadIdx.x;
    if (i < PN * NMEL) { int r = i / NMEL, c = i % NMEL; g_w1T[c * PN + r] = w[i]; }
}
__global__ void k_trans_w2(const float* __restrict__ w) {   // (256,256)
    int i = blockIdx.x * blockDim.x + threadIdx.x;
    if (i < PN * PN) { int r = i / PN, c = i % PN; g_w2T[c * PN + r] = w[i]; }
}
__global__ void k_trans_wk(const float* __restrict__ w) {   // (128,512) -> [k][d]
    int i = blockIdx.x * blockDim.x + threadIdx.x;
    if (i < AD * EMB) { int r = i / EMB, c = i % EMB; g_wkT[c * AD + r] = w[i]; }
}

// prenet for one timestep t per block: 256 threads, thread m covers all 32 b
__global__ __launch_bounds__(256) void k_prenet(const float* __restrict__ dec_inputs) {
    __shared__ float sin_[B][NMEL];
    __shared__ float sh1[B][PN];
    int t = blockIdx.x;
    int tid = threadIdx.x;
    for (int i = tid; i < B * NMEL; i += 256) {
        int b = i / NMEL, k = i % NMEL;
        sin_[b][k] = (t == 0) ? 0.0f
                   : dec_inputs[((size_t)b * TOUT + (t - 1)) * NMEL + k];
    }
    __syncthreads();
    int m = tid;
    float acc[B];
#pragma unroll
    for (int b = 0; b < B; ++b) acc[b] = 0.0f;
    for (int k = 0; k < NMEL; ++k) {
        float wv_ = g_w1T[k * PN + m];
#pragma unroll
        for (int b = 0; b < B; ++b) acc[b] = fmaf(wv_, sin_[b][k], acc[b]);
    }
#pragma unroll
    for (int b = 0; b < B; ++b) sh1[b][m] = fmaxf(acc[b], 0.0f);
    __syncthreads();
#pragma unroll
    for (int b = 0; b < B; ++b) acc[b] = 0.0f;
    for (int k = 0; k < PN; ++k) {
        float wv_ = g_w2T[k * PN + m];
#pragma unroll
        for (int b = 0; b < B; ++b) acc[b] = fmaf(wv_, sh1[b][k], acc[b]);
    }
#pragma unroll
    for (int b = 0; b < B; ++b)
        g_xs[((size_t)t * B + b) * PN + m] = fmaxf(acc[b], 0.0f);
}

// keys: block = (b, group of 8 t); 128 threads (thread = d)
__global__ __launch_bounds__(128) void k_keys(const float* __restrict__ memory) {
    __shared__ float sm[8][EMB];
    int b  = blockIdx.x >> 5;
    int t0 = (blockIdx.x & 31) * 8;
    int tid = threadIdx.x;
    for (int i = tid; i < 8 * EMB; i += 128) {
        int j = i >> 9, k = i & 511;
        sm[j][k] = memory[((size_t)b * TENC + t0 + j) * EMB + k];
    }
    __syncthreads();
    int d = tid;
    float acc[8];
#pragma unroll
    for (int j = 0; j < 8; ++j) acc[j] = 0.0f;
    for (int k = 0; k < EMB; ++k) {
        float wv_ = g_wkT[k * AD + d];
#pragma unroll
        for (int j = 0; j < 8; ++j) acc[j] = fmaf(wv_, sm[j][k], acc[j]);
    }
#pragma unroll
    for (int j = 0; j < 8; ++j)
        g_keys[((size_t)b * TENC + t0 + j) * AD + d] = acc[j];
}

// ---------------- persistent decoder ----------------
__global__ __launch_bounds__(NTHR) void k_decoder(Params p) {
    __shared__ float sq[AD];
    __shared__ float se[TENC];
    __shared__ float sw_[TENC];
    __shared__ float sred[2];

    const int tid  = threadIdx.x;
    const int lane = tid & 31;
    const int warp = tid >> 5;
    const int gw   = blockIdx.x * 16 + warp;

    // ---- zero-init state (deterministic per launch) ----
    {
        const int tot = blockDim.x * gridDim.x;
        const int gt  = blockIdx.x * blockDim.x + tid;
        for (int i = gt; i < 2 * B * ARNN; i += tot) { g_ah[0][i] = 0.f; }  // covers g_ah[0..1] contiguously
        for (int i = gt; i < B * ARNN; i += tot) g_ac[i] = 0.f;
        for (int i = gt; i < 2 * B * DRNN; i += tot) { g_dh[0][i] = 0.f; }
        for (int i = gt; i < B * DRNN; i += tot) g_dc[i] = 0.f;
        for (int i = gt; i < 2 * B * EMB; i += tot) { g_ctx[0][i] = 0.f; }
        for (int i = gt; i < B * TENC; i += tot) { g_aw[i] = 0.f; g_awc[i] = 0.f; }
    }
    grid_sync();

    for (int t = 0; t <= TOUT; ++t) {
        const int rp = (t + 1) & 1;   // "previous" parity
        const int wp = t & 1;         // "current" parity
        const float* ah_rd  = g_ah[rp];   // ah(t-1)
        float*       ah_wr  = g_ah[wp];   // ah(t)
        const float* dh_rd  = g_dh[wp];   // dh(t-2)
        float*       dh_wr  = g_dh[rp];   // dh(t-1)
        const float* ctx_rd = g_ctx[rp];  // ctx(t-1)
        float*       ctx_wr = g_ctx[wp];  // ctx(t)

        // ================= Phase A =================
        {
            int base = (t == TOUT) ? (ATT_TASKS + CONV_TASKS) : 0;
            int n;
            if (t == 0)         n = ATT_TASKS + CONV_TASKS;
            else if (t == TOUT) n = DEC_TASKS;
            else                n = PA_ALL;

            for (int id0 = gw; id0 < n; id0 += NWRP) {
                int id = id0 + base;
                if (id < ATT_TASKS) {
                    // ---- attention LSTM, unit u batch b ----
                    int u = id >> 5, b = id & 31;
                    const float* xrow = g_xs + ((size_t)t * B + b) * PN;
                    const float* crow = ctx_rd + b * EMB;
                    const float* hrow = ah_rd + b * ARNN;
                    float acc[4];
#pragma unroll
                    for (int g = 0; g < 4; ++g) {
                        const float* wi = p.att_wih + (size_t)((g << 10) + u) * (PN + EMB);
                        const float* wh = p.att_whh + (size_t)((g << 10) + u) * ARNN;
                        float a = 0.f;
                        a = dot4(wi, xrow, PN / 4, a, lane);
                        a = dot4(wi + PN, crow, EMB / 4, a, lane);
                        a = dot4(wh, hrow, ARNN / 4, a, lane);
                        acc[g] = wredsum(a);
                    }
                    if (lane == 0) {
                        float gi = acc[0] + p.att_bih[u]          + p.att_bhh[u];
                        float gf = acc[1] + p.att_bih[1024 + u]   + p.att_bhh[1024 + u];
                        float gg = acc[2] + p.att_bih[2048 + u]   + p.att_bhh[2048 + u];
                        float go = acc[3] + p.att_bih[3072 + u]   + p.att_bhh[3072 + u];
                        float c2 = sig_(gf) * g_ac[b * ARNN + u] + sig_(gi) * tanhf(gg);
                        g_ac[b * ARNN + u] = c2;
                        ah_wr[b * ARNN + u] = sig_(go) * tanhf(c2);
                    }
                } else if (id < ATT_TASKS + CONV_TASKS) {
                    // ---- location conv + wloc projection, (b, tt), lane = filter ----
                    int cid = id - ATT_TASKS;
                    int b = cid >> 8, tt = cid & 255;
                    const float* cw0 = p.conv_w + lane * (2 * KSZ);
                    float cv = p.conv_b[lane];
#pragma unroll
                    for (int k = 0; k < KSZ; ++k) {
                        int pp = tt + k - 15;
                        if (pp >= 0 && pp < TENC) {
                            cv = fmaf(cw0[k],        g_aw[b * TENC + pp], cv);
                            cv = fmaf(cw0[KSZ + k],  g_awc[b * TENC + pp], cv);
                        }
                    }
                    float a0 = 0.f, a1 = 0.f, a2 = 0.f, a3 = 0.f;
#pragma unroll
                    for (int src = 0; src < 32; ++src) {
                        float v = __shfl_sync(0xffffffffu, cv, src);
                        a0 = fmaf(v, p.wloc[(lane)       * NF + src], a0);
                        a1 = fmaf(v, p.wloc[(lane + 32)  * NF + src], a1);
                        a2 = fmaf(v, p.wloc[(lane + 64)  * NF + src], a2);
                        a3 = fmaf(v, p.wloc[(lane + 96)  * NF + src], a3);
                    }
                    size_t o = ((size_t)b * TENC + tt) * AD;
                    g_loc[o + lane]      = a0;
                    g_loc[o + lane + 32] = a1;
                    g_loc[o + lane + 64] = a2;
                    g_loc[o + lane + 96] = a3;
                } else {
                    // ---- decoder LSTM for step t-1, unit u batch b ----
                    int did = id - (ATT_TASKS + CONV_TASKS);
                    int u = did >> 5, b = did & 31;
                    const float* arow = ah_rd + b * ARNN;   // ah(t-1)
                    const float* crow = ctx_rd + b * EMB;   // ctx(t-1)
                    const float* hrow = dh_rd + b * DRNN;   // dh(t-2)
                    float acc[4];
#pragma unroll
                    for (int g = 0; g < 4; ++g) {
                        const float* wi = p.dec_wih + (size_t)((g << 10) + u) * (ARNN + EMB);
                        const float* wh = p.dec_whh + (size_t)((g << 10) + u) * DRNN;
                        float a = 0.f;
                        a = dot4(wi, arow, ARNN / 4, a, lane);
                        a = dot4(wi + ARNN, crow, EMB / 4, a, lane);
                        a = dot4(wh, hrow, DRNN / 4, a, lane);
                        acc[g] = wredsum(a);
                    }
                    if (lane == 0) {
                        float gi = acc[0] + p.dec_bih[u]        + p.dec_bhh[u];
                        float gf = acc[1] + p.dec_bih[1024 + u] + p.dec_bhh[1024 + u];
                        float gg = acc[2] + p.dec_bih[2048 + u] + p.dec_bhh[2048 + u];
                        float go = acc[3] + p.dec_bih[3072 + u] + p.dec_bhh[3072 + u];
                        float c2 = sig_(gf) * g_dc[b * DRNN + u] + sig_(gi) * tanhf(gg);
                        g_dc[b * DRNN + u] = c2;
                        dh_wr[b * DRNN + u] = sig_(go) * tanhf(c2);
                    }
                }
            }
        }
        grid_sync();

        // ================= Phase B =================
        if (blockIdx.x < B) {
            if (t < TOUT) {
                const int b = blockIdx.x;
                // q = ah(t) @ wq^T : warp w -> d in [8w, 8w+8)
                const float* hrow = ah_wr + b * ARNN;   // ah(t)
#pragma unroll
                for (int j = 0; j < 8; ++j) {
                    int d = warp * 8 + j;
                    float a = dot4(p.wq + (size_t)d * ARNN, hrow, ARNN / 4, 0.f, lane);
                    a = wredsum(a);
                    if (lane == 0) sq[d] = a;
                }
                __syncthreads();
                // energies
                const int len = p.mlen[b];
#pragma unroll
                for (int j = 0; j < 16; ++j) {
                    int tt = warp + j * 16;
                    size_t o = ((size_t)b * TENC + tt) * AD;
                    float a = 0.f;
#pragma unroll
                    for (int jj = 0; jj < 4; ++jj) {
                        int d = lane + jj * 32;
                        float s = sq[d] + g_keys[o + d] + g_loc[o + d];
                        a = fmaf(p.wv[d], tanhf(s), a);
                    }
                    a = wredsum(a);
                    if (lane == 0) se[tt] = (tt >= len) ? -1e9f : a;
                }
                __syncthreads();
                // softmax stats (warp 0)
                if (warp == 0) {
                    float m = -3.4e38f;
#pragma unroll
                    for (int j = 0; j < 8; ++j) m = fmaxf(m, se[lane + j * 32]);
#pragma unroll
                    for (int o = 16; o > 0; o >>= 1)
                        m = fmaxf(m, __shfl_xor_sync(0xffffffffu, m, o));
                    float s = 0.f;
#pragma unroll
                    for (int j = 0; j < 8; ++j) s += expf(se[lane + j * 32] - m);
                    s = wredsum(s);
                    if (lane == 0) { sred[0] = m; sred[1] = 1.0f / s; }
                }
                __syncthreads();
                if (tid < TENC) {
                    float w = expf(se[tid] - sred[0]) * sred[1];
                    sw_[tid] = w;
                    g_aw[b * TENC + tid] = w;
                    g_awc[b * TENC + tid] += w;
                    p.out[ALIGN_OFF + ((size_t)b * TOUT + t) * TENC + tid] = w;
                }
                __syncthreads();
                // ctx(t): warp w handles e in [32w, 32w+32)
                {
                    int e = warp * 32 + lane;
                    const float* mb = p.memory + (size_t)b * TENC * EMB + e;
                    float acc = 0.f;
#pragma unroll 8
                    for (int tt = 0; tt < TENC; ++tt)
                        acc = fmaf(sw_[tt], mb[(size_t)tt * EMB], acc);
                    ctx_wr[b * EMB + e] = acc;
                }
            }
        } else if (t > 0) {
            // projection for step t-1: warps of blocks 32..147
            int pgw = (blockIdx.x - B) * 16 + warp;
            for (int id = pgw; id < PROJ_TASKS; id += (NBLK - B) * 16) {
                int row = id >> 5, b = id & 31;
                const float* hrow = dh_wr + b * DRNN;    // dh(t-1)
                const float* crow = ctx_rd + b * EMB;    // ctx(t-1)
                const float* wr; float bias;
                if (row < NMEL) { wr = p.wproj + (size_t)row * (DRNN + EMB); bias = p.bproj[row]; }
                else            { wr = p.wgate;                               bias = p.bgate[0]; }
                float a = 0.f;
                a = dot4(wr, hrow, DRNN / 4, a, lane);
                a = dot4(wr + DRNN, crow, EMB / 4, a, lane);
                a = wredsum(a) + bias;
                if (lane == 0) {
                    if (row < NMEL)
                        p.out[((size_t)b * NMEL + row) * TOUT + (t - 1)] = a;
                    else
                        p.out[GATE_OFF + (size_t)b * TOUT + (t - 1)] = a;
                }
            }
        }
        grid_sync();
    }
}

// ---------------- launch ----------------
extern "C" void kernel_launch(void* const* d_in, const int* in_sizes, int n_in,
                              void* d_out, int out_size) {
    Params p;
    p.memory     = (const float*)d_in[0];
    p.dec_inputs = (const float*)d_in[1];
    p.mlen       = (const int*)  d_in[2];
    const float* prenet_w1 = (const float*)d_in[3];
    const float* prenet_w2 = (const float*)d_in[4];
    p.att_wih    = (const float*)d_in[5];
    p.att_whh    = (const float*)d_in[6];
    p.att_bih    = (const float*)d_in[7];
    p.att_bhh    = (const float*)d_in[8];
    p.wq         = (const float*)d_in[9];
    const float* wk = (const float*)d_in[10];
    p.conv_w     = (const float*)d_in[11];
    p.conv_b     = (const float*)d_in[12];
    p.wloc       = (const float*)d_in[13];
    p.wv         = (const float*)d_in[14];
    p.dec_wih    = (const float*)d_in[15];
    p.dec_whh    = (const float*)d_in[16];
    p.dec_bih    = (const float*)d_in[17];
    p.dec_bhh    = (const float*)d_in[18];
    p.wproj      = (const float*)d_in[19];
    p.bproj      = (const float*)d_in[20];
    p.wgate      = (const float*)d_in[21];
    p.bgate      = (const float*)d_in[22];
    p.out        = (float*)d_out;

    k_trans_w1<<<(PN * NMEL + 255) / 256, 256>>>(prenet_w1);
    k_trans_w2<<<(PN * PN + 255) / 256, 256>>>(prenet_w2);
    k_trans_wk<<<(AD * EMB + 255) / 256, 256>>>(wk);
    k_prenet<<<TOUT, 256>>>(p.dec_inputs);
    k_keys<<<B * (TENC / 8), 128>>>(p.memory);
    k_decoder<<<NBLK, NTHR>>>(p);
}